// round 11
// baseline (speedup 1.0000x reference)
#include <cuda_runtime.h>

// SqueezeSeg Recurrent CRF — fully fused 3-iteration kernel, sm_103a. Round 5.
// B=16, C=4, H=64, W=512, 3x5 neighborhood (14 neighbors), 3 CRF iterations
// in ONE kernel launch.
//
// Design:
//  - Each CTA covers the FULL H (64 rows) and TW=16 output columns of one
//    batch image. Region = 28 cols (TW + 2*6 halo for 3 iters) x 66 rows
//    (H + zero rows at top/bottom for H-halo).
//  - Iteration n computes a region that shrinks by 4 cols (2 each side);
//    widths 24 -> 20 -> 16. In-place s_u update between syncs is safe since
//    iter n+1 only reads cells iter n wrote (or permanent zeros).
//  - 512 CTAs x 256 thr, 37KB smem, launch_bounds(256,4): all CTAs resident,
//    single wave, one launch -> no inter-kernel tails or intermediate
//    global x round-trips.
//  - Packed fma.rn.f32x2 accumulation (R4).
//
// Math notes (verified vs reference):
//  - ANG_THETA_A == BILATERAL_THETA_A => g_ang == g_bi => bi_ang == ang.
//  - compat = ones - eye => out[o] = unary[o] + 0.02*(sum_ang - ang[o])
//                                   + 0.10*(sum_bi - bi[o]).
//  - Zero padding: OOB cells hold u=0, m=0 forever (never written).

#define BATCH 16
#define NC 4
#define HH 64
#define WW 512
#define PLANE (HH*WW)

#define TW 16         // output cols per CTA
#define REGC 28       // region cols = TW + 12
#define REGR 66       // rows: r = h+1, r in [0,65]; rows 0,65 stay zero
#define NTH 256

typedef unsigned long long u64t;

__device__ __forceinline__ u64t ffma2(u64t a, u64t b, u64t c) {
    u64t d;
    asm("fma.rn.f32x2 %0, %1, %2, %3;" : "=l"(d) : "l"(a), "l"(b), "l"(c));
    return d;
}
__device__ __forceinline__ u64t pack2(float lo, float hi) {
    u64t d;
    asm("mov.b64 %0, {%1, %2};" : "=l"(d) : "f"(lo), "f"(hi));
    return d;
}
__device__ __forceinline__ void unpack2(u64t v, float& lo, float& hi) {
    asm("mov.b64 {%0, %1}, %2;" : "=f"(lo), "=f"(hi) : "l"(v));
}

// One CRF iteration over a shrinking region.
// OUTW: output width (24/20/16), COL0: first local output col (2/4/6).
// FINAL=false: write softmax(x') back into s_u (between two barriers).
// FINAL=true : write raw x' to global out.
template<int OUTW, int COL0, bool FINAL>
__device__ __forceinline__ void crf_step(
    float4 (*s_u)[REGC], float (*s_m)[REGC],
    const float* __restrict__ bfb,   // bf + b*14*PLANE
    float* __restrict__ outb,        // out + b*4*PLANE
    int wbase, int tid, const u64t* g2)
{
    constexpr int NPX = HH * OUTW;
    constexpr int PPT = NPX / NTH;       // 6 / 5 / 4 (all exact)

    // neighbor offsets (dz, da) of 3x5 kernel, center excluded; d2 -> g index
    const int offz[14] = {0,0,0,0,0, 1,1,1,1, 2,2,2,2,2};
    const int offa[14] = {0,1,2,3,4, 0,1,3,4, 0,1,2,3,4};

    float4 st[PPT];

    #pragma unroll
    for (int i = 0; i < PPT; ++i) {
        const int p   = tid + i * NTH;
        const int row = p / OUTW;          // global h
        const int jc  = p % OUTW + COL0;   // local col
        const int w   = wbase + jc;        // global w
        const int r   = row + 1;           // local smem row

        if (w < 0 || w >= WW) continue;    // OOB column: skip (cell stays 0)

        const int off = row * WW + w;
        const float* bfp = bfb + off;

        u64t ang_lo = 0, ang_hi = 0, cond_lo = 0, cond_hi = 0;

        #pragma unroll
        for (int k = 0; k < 14; ++k) {
            const int dz = offz[k];
            const int da = offa[k];
            const int d2 = (dz - 1) * (dz - 1) + (da - 2) * (da - 2);
            const int gi = (d2 == 1) ? 0 : (d2 == 2) ? 1 : (d2 == 4) ? 2 : 3;
            const int sh = r - 1 + dz;
            const int sw = jc + da - 2;
            const ulonglong2 u2 = *reinterpret_cast<const ulonglong2*>(&s_u[sh][sw]);
            const float m  = s_m[sh][sw];
            const float bm = bfp[k * PLANE] * m;
            const u64t bm2 = pack2(bm, bm);
            ang_lo  = ffma2(g2[gi], u2.x, ang_lo);
            ang_hi  = ffma2(g2[gi], u2.y, ang_hi);
            cond_lo = ffma2(bm2,    u2.x, cond_lo);
            cond_hi = ffma2(bm2,    u2.y, cond_hi);
        }

        float a0, a1, a2, a3, c0, c1, c2, c3;
        unpack2(ang_lo,  a0, a1);
        unpack2(ang_hi,  a2, a3);
        unpack2(cond_lo, c0, c1);
        unpack2(cond_hi, c2, c3);

        const float mc = s_m[r][jc];
        const float b0 = c0 * mc * a0;     // bi_ang == ang
        const float b1 = c1 * mc * a1;
        const float b2 = c2 * mc * a2;
        const float b3 = c3 * mc * a3;
        const float sa = a0 + a1 + a2 + a3;
        const float sb = b0 + b1 + b2 + b3;

        const float4 uc = s_u[r][jc];
        const float o0 = uc.x + 0.02f * (sa - a0) + 0.10f * (sb - b0);
        const float o1 = uc.y + 0.02f * (sa - a1) + 0.10f * (sb - b1);
        const float o2 = uc.z + 0.02f * (sa - a2) + 0.10f * (sb - b2);
        const float o3 = uc.w + 0.02f * (sa - a3) + 0.10f * (sb - b3);

        if (FINAL) {
            outb[0 * PLANE + off] = o0;
            outb[1 * PLANE + off] = o1;
            outb[2 * PLANE + off] = o2;
            outb[3 * PLANE + off] = o3;
        } else {
            // softmax now; write back after barrier
            const float mx = fmaxf(fmaxf(o0, o1), fmaxf(o2, o3));
            float u0 = __expf(o0 - mx);
            float u1 = __expf(o1 - mx);
            float u2v = __expf(o2 - mx);
            float u3 = __expf(o3 - mx);
            const float inv = 1.0f / (u0 + u1 + u2v + u3);
            st[i] = make_float4(u0 * inv, u1 * inv, u2v * inv, u3 * inv);
        }
    }

    if (!FINAL) {
        __syncthreads();   // all stencil reads done before any write
        #pragma unroll
        for (int i = 0; i < PPT; ++i) {
            const int p   = tid + i * NTH;
            const int row = p / OUTW;
            const int jc  = p % OUTW + COL0;
            const int w   = wbase + jc;
            if (w < 0 || w >= WW) continue;
            s_u[row + 1][jc] = st[i];
        }
        __syncthreads();   // writes visible before next iteration reads
    }
}

__global__ __launch_bounds__(NTH, 4)
void crf_fused_kernel(const float* __restrict__ x,
                      const float* __restrict__ bf,     // [B,14,H,W]
                      const float* __restrict__ mask,   // [B,H,W]
                      float* __restrict__ out)          // [B,4,H,W]
{
    __shared__ float4 s_u[REGR][REGC];
    __shared__ float  s_m[REGR][REGC];

    const int b     = blockIdx.y;
    const int wbase = blockIdx.x * TW - 6;   // local col j -> global w = wbase + j
    const int tid   = threadIdx.x;

    const float* xb  = x    + (size_t)b * NC * PLANE;
    const float* mb  = mask + (size_t)b * PLANE;
    const float* bfb = bf   + (size_t)b * 14 * PLANE;
    float*       ob  = out  + (size_t)b * NC * PLANE;

    // ---- Phase 1: load x region, softmax, load mask; zeros for OOB cells
    for (int i = tid; i < REGR * REGC; i += NTH) {
        const int r = i / REGC;
        const int j = i % REGC;
        const int h = r - 1;
        const int w = wbase + j;
        float4 u = make_float4(0.f, 0.f, 0.f, 0.f);
        float m = 0.f;
        if (h >= 0 && h < HH && w >= 0 && w < WW) {
            const int off = h * WW + w;
            const float a0 = xb[0 * PLANE + off];
            const float a1 = xb[1 * PLANE + off];
            const float a2 = xb[2 * PLANE + off];
            const float a3 = xb[3 * PLANE + off];
            const float mx = fmaxf(fmaxf(a0, a1), fmaxf(a2, a3));
            u.x = __expf(a0 - mx);
            u.y = __expf(a1 - mx);
            u.z = __expf(a2 - mx);
            u.w = __expf(a3 - mx);
            const float inv = 1.0f / (u.x + u.y + u.z + u.w);
            u.x *= inv; u.y *= inv; u.z *= inv; u.w *= inv;
            m = mb[off];
        }
        s_u[r][j] = u;
        s_m[r][j] = m;
    }
    __syncthreads();

    // Gaussian weights: d2 in {1,2,4,5}, denom 2*0.9^2 = 1.62
    const float inv_den = 1.0f / 1.62f;
    const float e1 = __expf(-1.0f * inv_den);
    const float e2 = __expf(-2.0f * inv_den);
    const float e4 = __expf(-4.0f * inv_den);
    const float e5 = __expf(-5.0f * inv_den);
    const u64t g2[4] = { pack2(e1, e1), pack2(e2, e2), pack2(e4, e4), pack2(e5, e5) };

    // ---- 3 CRF iterations, shrinking region: 24 -> 20 -> 16 output cols
    crf_step<24, 2, false>(s_u, s_m, bfb, ob, wbase, tid, g2);
    crf_step<20, 4, false>(s_u, s_m, bfb, ob, wbase, tid, g2);
    crf_step<16, 6, true >(s_u, s_m, bfb, ob, wbase, tid, g2);
}

extern "C" void kernel_launch(void* const* d_in, const int* in_sizes, int n_in,
                              void* d_out, int out_size)
{
    const float* x    = (const float*)d_in[0];  // [16,4,64,512]
    const float* bf   = (const float*)d_in[1];  // [16,1,14,64,512]
    const float* mask = (const float*)d_in[2];  // [16,1,64,512]
    float* out = (float*)d_out;

    dim3 block(NTH, 1, 1);                 // 256 threads
    dim3 grid(WW / TW, BATCH, 1);          // 32 x 16 = 512 blocks, single wave

    crf_fused_kernel<<<grid, block>>>(x, bf, mask, out);
}

// round 13
// speedup vs baseline: 1.3282x; 1.3282x over previous
#include <cuda_runtime.h>

// SqueezeSeg Recurrent CRF — per-iteration kernel chain, sm_103a. Round 6b.
// B=16, C=4, H=64, W=512, 3x5 neighborhood (14 neighbors), 3 iterations.
//
// R6b = R6 with the L2 hint fixed: scalar evict_last needs the
// createpolicy + ld.global.nc.L2::cache_hint form on sm_103 (bare
// .L2::evict_last is only legal on 256-bit vector loads).
//
//  - Kernels pass SOFTMAXED unary between iterations as interleaved float4
//    [B,H,W,4]: phase-1 of iters 2-3 is one coalesced LDG.128 (no softmax,
//    no 4x planar loads); softmax computed once per owned pixel in the
//    epilogue of iters 1-2 (was 1.33x-redundant in the halo phase).
//  - bf loads carry an L2 evict_last cache-policy hint (bf is streamed by
//    all 3 kernels; whole working set ~54MB fits in 126MB L2).
//  - Packed fma.rn.f32x2 stencil accumulation.
//
// Math notes (verified vs reference):
//  - ANG_THETA_A == BILATERAL_THETA_A => g_ang == g_bi => bi_ang == ang.
//  - compat = ones - eye => out[o] = unary[o] + 0.02*(sum_ang - ang[o])
//                                   + 0.10*(sum_bi - bi[o]).

#define BATCH 16
#define NC 4
#define HH 64
#define WW 512
#define PLANE (HH*WW)

#define TH 8
#define TW 64
#define SH (TH + 2)   // halo 1 in H
#define SW (TW + 4)   // halo 2 in W
#define NTHREADS (TH * TW)   // 512

typedef unsigned long long u64t;

__device__ __forceinline__ u64t ffma2(u64t a, u64t b, u64t c) {
    u64t d;
    asm("fma.rn.f32x2 %0, %1, %2, %3;" : "=l"(d) : "l"(a), "l"(b), "l"(c));
    return d;
}
__device__ __forceinline__ u64t pack2(float lo, float hi) {
    u64t d;
    asm("mov.b64 %0, {%1, %2};" : "=l"(d) : "f"(lo), "f"(hi));
    return d;
}
__device__ __forceinline__ void unpack2(u64t v, float& lo, float& hi) {
    asm("mov.b64 {%0, %1}, %2;" : "=f"(lo), "=f"(hi) : "l"(v));
}
// L2 evict_last policy (fractional 1.0) — created once per thread.
__device__ __forceinline__ u64t mk_policy_keep() {
    u64t pol;
    asm("createpolicy.fractional.L2::evict_last.b64 %0, 1.0;" : "=l"(pol));
    return pol;
}
__device__ __forceinline__ float ldg_keep(const float* p, u64t pol) {
    float v;
    asm("ld.global.nc.L2::cache_hint.f32 %0, [%1], %2;"
        : "=f"(v) : "l"(p), "l"(pol));
    return v;
}

// interleaved softmaxed-unary scratch: [B,H,W] of float4
__device__ float4 g_uA[BATCH * PLANE];
__device__ float4 g_uB[BATCH * PLANE];

// IN_PLANAR:  input is raw planar x [B,4,H,W] -> softmax in phase 1.
//             else input is interleaved softmaxed u [B,H,W,4].
// OUT_PLANAR: output raw planar x' [B,4,H,W] (final iteration).
//             else output softmax(x') interleaved (intermediate).
template<bool IN_PLANAR, bool OUT_PLANAR>
__global__ __launch_bounds__(NTHREADS)
void crf_iter_kernel(const float* __restrict__ xin,     // planar or (float4*)
                     const float* __restrict__ bf,      // [B,14,H,W]
                     const float* __restrict__ mask,    // [B,H,W]
                     float* __restrict__ xout)          // planar or (float4*)
{
    __shared__ float4 s_u[SH][SW];
    __shared__ float  s_m[SH][SW];

    const int b  = blockIdx.z;
    const int h0 = blockIdx.y * TH;
    const int w0 = blockIdx.x * TW;
    const int tx = threadIdx.x;   // 0..63 along W
    const int ty = threadIdx.y;   // 0..7 along H
    const int tid = ty * TW + tx;

    const float* mb = mask + (size_t)b * PLANE;

    // ---- Phase 1: load unary region into smem (tile+halo)
    #pragma unroll
    for (int i = tid; i < SH * SW; i += NTHREADS) {
        const int sh = i / SW;
        const int sw = i % SW;
        const int h = h0 + sh - 1;
        const int w = w0 + sw - 2;
        float4 u = make_float4(0.f, 0.f, 0.f, 0.f);
        float m = 0.f;
        if (h >= 0 && h < HH && w >= 0 && w < WW) {
            const int off = h * WW + w;
            if (IN_PLANAR) {
                const float* xb = xin + (size_t)b * NC * PLANE;
                const float a0 = xb[0 * PLANE + off];
                const float a1 = xb[1 * PLANE + off];
                const float a2 = xb[2 * PLANE + off];
                const float a3 = xb[3 * PLANE + off];
                const float mx = fmaxf(fmaxf(a0, a1), fmaxf(a2, a3));
                u.x = __expf(a0 - mx);
                u.y = __expf(a1 - mx);
                u.z = __expf(a2 - mx);
                u.w = __expf(a3 - mx);
                const float inv = 1.0f / (u.x + u.y + u.z + u.w);
                u.x *= inv; u.y *= inv; u.z *= inv; u.w *= inv;
            } else {
                const float4* ub = (const float4*)xin + (size_t)b * PLANE;
                u = ub[off];
            }
            m = mb[off];
        }
        s_u[sh][sw] = u;
        s_m[sh][sw] = m;
    }
    __syncthreads();

    // ---- Phase 2: stencil (1 px per thread), packed f32x2 accumulation
    const int h = h0 + ty;
    const int w = w0 + tx;
    const int off = h * WW + w;

    // Gaussian weights: d2 in {1,2,4,5}, denom 2*0.9^2 = 1.62
    const float inv_den = 1.0f / 1.62f;
    const float e1 = __expf(-1.0f * inv_den);
    const float e2 = __expf(-2.0f * inv_den);
    const float e4 = __expf(-4.0f * inv_den);
    const float e5 = __expf(-5.0f * inv_den);
    const u64t g2[4] = { pack2(e1, e1), pack2(e2, e2), pack2(e4, e4), pack2(e5, e5) };

    const u64t pol = mk_policy_keep();
    const float* bfp = bf + (size_t)b * 14 * PLANE + off;

    u64t ang_lo  = 0;   // classes 0,1
    u64t ang_hi  = 0;   // classes 2,3
    u64t cond_lo = 0;
    u64t cond_hi = 0;

    const int offz[14] = {0,0,0,0,0, 1,1,1,1, 2,2,2,2,2};
    const int offa[14] = {0,1,2,3,4, 0,1,3,4, 0,1,2,3,4};

    #pragma unroll
    for (int k = 0; k < 14; ++k) {
        const int dz = offz[k];
        const int da = offa[k];
        const int d2 = (dz - 1) * (dz - 1) + (da - 2) * (da - 2);
        const int gi = (d2 == 1) ? 0 : (d2 == 2) ? 1 : (d2 == 4) ? 2 : 3;
        const int sh = ty + dz;
        const int sw = tx + da;
        const ulonglong2 u2 = *reinterpret_cast<const ulonglong2*>(&s_u[sh][sw]);
        const float m  = s_m[sh][sw];
        const float bm = ldg_keep(bfp + k * PLANE, pol) * m;
        const u64t bm2 = pack2(bm, bm);
        ang_lo  = ffma2(g2[gi], u2.x, ang_lo);
        ang_hi  = ffma2(g2[gi], u2.y, ang_hi);
        cond_lo = ffma2(bm2,    u2.x, cond_lo);
        cond_hi = ffma2(bm2,    u2.y, cond_hi);
    }

    // ---- Epilogue
    float a0, a1, a2, a3, c0, c1, c2, c3;
    unpack2(ang_lo,  a0, a1);
    unpack2(ang_hi,  a2, a3);
    unpack2(cond_lo, c0, c1);
    unpack2(cond_hi, c2, c3);

    const float mc = s_m[ty + 1][tx + 2];
    const float b0 = c0 * mc * a0;     // bi_ang == ang (equal thetas)
    const float b1 = c1 * mc * a1;
    const float b2 = c2 * mc * a2;
    const float b3 = c3 * mc * a3;
    const float sa = a0 + a1 + a2 + a3;
    const float sb = b0 + b1 + b2 + b3;

    const float4 uc = s_u[ty + 1][tx + 2];
    const float o0 = uc.x + 0.02f * (sa - a0) + 0.10f * (sb - b0);
    const float o1 = uc.y + 0.02f * (sa - a1) + 0.10f * (sb - b1);
    const float o2 = uc.z + 0.02f * (sa - a2) + 0.10f * (sb - b2);
    const float o3 = uc.w + 0.02f * (sa - a3) + 0.10f * (sb - b3);

    if (OUT_PLANAR) {
        float* ob = xout + (size_t)b * NC * PLANE;
        ob[0 * PLANE + off] = o0;
        ob[1 * PLANE + off] = o1;
        ob[2 * PLANE + off] = o2;
        ob[3 * PLANE + off] = o3;
    } else {
        // softmax once here (next kernel consumes u directly)
        const float mx = fmaxf(fmaxf(o0, o1), fmaxf(o2, o3));
        float u0 = __expf(o0 - mx);
        float u1 = __expf(o1 - mx);
        float u2 = __expf(o2 - mx);
        float u3 = __expf(o3 - mx);
        const float inv = 1.0f / (u0 + u1 + u2 + u3);
        float4* ub = (float4*)xout + (size_t)b * PLANE;
        ub[off] = make_float4(u0 * inv, u1 * inv, u2 * inv, u3 * inv);
    }
}

extern "C" void kernel_launch(void* const* d_in, const int* in_sizes, int n_in,
                              void* d_out, int out_size)
{
    const float* x    = (const float*)d_in[0];  // [16,4,64,512]
    const float* bf   = (const float*)d_in[1];  // [16,1,14,64,512]
    const float* mask = (const float*)d_in[2];  // [16,1,64,512]
    float* out = (float*)d_out;

    float4* ua = nullptr;
    float4* ub = nullptr;
    cudaGetSymbolAddress((void**)&ua, g_uA);
    cudaGetSymbolAddress((void**)&ub, g_uB);

    dim3 block(TW, TH, 1);                  // 512 threads, 1 px/thread
    dim3 grid(WW / TW, HH / TH, BATCH);     // 8 x 8 x 16 = 1024 blocks

    crf_iter_kernel<true,  false><<<grid, block>>>(x,           bf, mask, (float*)ua);
    crf_iter_kernel<false, false><<<grid, block>>>((float*)ua,  bf, mask, (float*)ub);
    crf_iter_kernel<false, true ><<<grid, block>>>((float*)ub,  bf, mask, out);
}

// round 15
// speedup vs baseline: 1.4551x; 1.0955x over previous
#include <cuda_runtime.h>

// SqueezeSeg Recurrent CRF — per-iteration kernel chain, sm_103a. Round 7.
// B=16, C=4, H=64, W=512, 3x5 neighborhood (14 neighbors), 3 iterations.
//
// R7 = R6b + vertical register blocking (2 H-pixels per thread):
//  - The two pixels' stencils overlap on the middle 2 rows and read the SAME
//    smem columns -> each (row,col) cell is one LDS.128 + LDS.32, consumed by
//    both pixels with compile-time weights and bf-plane indices.
//    Per 2px: 20+20 smem loads (was 28+28) -> L1 wavefronts -24%.
//  - Interleaved softmaxed-unary handoff between iterations (float4
//    [B,H,W,4]); softmax computed once per pixel in the producing kernel.
//  - Packed fma.rn.f32x2 stencil accumulation.
//
// Math notes (verified vs reference):
//  - ANG_THETA_A == BILATERAL_THETA_A => g_ang == g_bi => bi_ang == ang.
//  - compat = ones - eye => out[o] = unary[o] + 0.02*(sum_ang - ang[o])
//                                   + 0.10*(sum_bi - bi[o]).

#define BATCH 16
#define NC 4
#define HH 64
#define WW 512
#define PLANE (HH*WW)

#define TH 8          // tile height
#define TW 64         // tile width
#define TYN 4         // threads in y; each covers 2 rows
#define SH (TH + 2)
#define SW (TW + 4)
#define NTH (TW * TYN)   // 256

typedef unsigned long long u64t;

__device__ __forceinline__ u64t ffma2(u64t a, u64t b, u64t c) {
    u64t d;
    asm("fma.rn.f32x2 %0, %1, %2, %3;" : "=l"(d) : "l"(a), "l"(b), "l"(c));
    return d;
}
__device__ __forceinline__ u64t pack2(float lo, float hi) {
    u64t d;
    asm("mov.b64 %0, {%1, %2};" : "=l"(d) : "f"(lo), "f"(hi));
    return d;
}
__device__ __forceinline__ void unpack2(u64t v, float& lo, float& hi) {
    asm("mov.b64 {%0, %1}, %2;" : "=f"(lo), "=f"(hi) : "l"(v));
}

// interleaved softmaxed-unary scratch: [B,H,W] of float4
__device__ float4 g_uA[BATCH * PLANE];
__device__ float4 g_uB[BATCH * PLANE];

template<bool OUT_PLANAR>
__device__ __forceinline__ void write_px(
    float* __restrict__ xout, int b, int off,
    u64t ang_lo, u64t ang_hi, u64t cond_lo, u64t cond_hi,
    float mc, float4 uc)
{
    float a0, a1, a2, a3, c0, c1, c2, c3;
    unpack2(ang_lo,  a0, a1);
    unpack2(ang_hi,  a2, a3);
    unpack2(cond_lo, c0, c1);
    unpack2(cond_hi, c2, c3);

    const float b0 = c0 * mc * a0;     // bi_ang == ang (equal thetas)
    const float b1 = c1 * mc * a1;
    const float b2 = c2 * mc * a2;
    const float b3 = c3 * mc * a3;
    const float sa = a0 + a1 + a2 + a3;
    const float sb = b0 + b1 + b2 + b3;

    const float o0 = uc.x + 0.02f * (sa - a0) + 0.10f * (sb - b0);
    const float o1 = uc.y + 0.02f * (sa - a1) + 0.10f * (sb - b1);
    const float o2 = uc.z + 0.02f * (sa - a2) + 0.10f * (sb - b2);
    const float o3 = uc.w + 0.02f * (sa - a3) + 0.10f * (sb - b3);

    if (OUT_PLANAR) {
        float* ob = xout + (size_t)b * NC * PLANE;
        ob[0 * PLANE + off] = o0;
        ob[1 * PLANE + off] = o1;
        ob[2 * PLANE + off] = o2;
        ob[3 * PLANE + off] = o3;
    } else {
        const float mx = fmaxf(fmaxf(o0, o1), fmaxf(o2, o3));
        float u0 = __expf(o0 - mx);
        float u1 = __expf(o1 - mx);
        float u2 = __expf(o2 - mx);
        float u3 = __expf(o3 - mx);
        const float inv = 1.0f / (u0 + u1 + u2 + u3);
        float4* ub = (float4*)xout + (size_t)b * PLANE;
        ub[off] = make_float4(u0 * inv, u1 * inv, u2 * inv, u3 * inv);
    }
}

// IN_PLANAR:  input raw planar x [B,4,H,W] (softmax in phase 1);
//             else interleaved softmaxed u [B,H,W,4].
// OUT_PLANAR: output raw planar x' (final); else softmax(x') interleaved.
template<bool IN_PLANAR, bool OUT_PLANAR>
__global__ __launch_bounds__(NTH, 5)
void crf_iter_kernel(const float* __restrict__ xin,
                     const float* __restrict__ bf,      // [B,14,H,W]
                     const float* __restrict__ mask,    // [B,H,W]
                     float* __restrict__ xout)
{
    __shared__ float4 s_u[SH][SW];
    __shared__ float  s_m[SH][SW];

    const int b  = blockIdx.z;
    const int h0 = blockIdx.y * TH;
    const int w0 = blockIdx.x * TW;
    const int tx = threadIdx.x;   // 0..63 along W
    const int ty = threadIdx.y;   // 0..3 -> rows 2ty, 2ty+1
    const int tid = ty * TW + tx;

    const float* mb = mask + (size_t)b * PLANE;

    // ---- Phase 1: load unary region into smem (tile+halo)
    #pragma unroll
    for (int i = tid; i < SH * SW; i += NTH) {
        const int sh = i / SW;
        const int sw = i % SW;
        const int h = h0 + sh - 1;
        const int w = w0 + sw - 2;
        float4 u = make_float4(0.f, 0.f, 0.f, 0.f);
        float m = 0.f;
        if (h >= 0 && h < HH && w >= 0 && w < WW) {
            const int off = h * WW + w;
            if (IN_PLANAR) {
                const float* xb = xin + (size_t)b * NC * PLANE;
                const float a0 = xb[0 * PLANE + off];
                const float a1 = xb[1 * PLANE + off];
                const float a2 = xb[2 * PLANE + off];
                const float a3 = xb[3 * PLANE + off];
                const float mx = fmaxf(fmaxf(a0, a1), fmaxf(a2, a3));
                u.x = __expf(a0 - mx);
                u.y = __expf(a1 - mx);
                u.z = __expf(a2 - mx);
                u.w = __expf(a3 - mx);
                const float inv = 1.0f / (u.x + u.y + u.z + u.w);
                u.x *= inv; u.y *= inv; u.z *= inv; u.w *= inv;
            } else {
                const float4* ub = (const float4*)xin + (size_t)b * PLANE;
                u = ub[off];
            }
            m = mb[off];
        }
        s_u[sh][sw] = u;
        s_m[sh][sw] = m;
    }
    __syncthreads();

    // ---- Phase 2: stencil, 2 vertically-adjacent pixels per thread
    // Gaussian weights: d2 in {1,2,4,5}, denom 2*0.9^2 = 1.62
    const float inv_den = 1.0f / 1.62f;
    const float e1 = __expf(-1.0f * inv_den);
    const float e2 = __expf(-2.0f * inv_den);
    const float e4 = __expf(-4.0f * inv_den);
    const float e5 = __expf(-5.0f * inv_den);
    const u64t g2[4] = { pack2(e1, e1), pack2(e2, e2), pack2(e4, e4), pack2(e5, e5) };

    // per-dz weight index into g2 and bf k-plane index (compile-time folded)
    const signed char gidx[3][5] = { {3,1,0,1,3}, {2,0,0,0,2}, {3,1,0,1,3} };
    const signed char ktab[3][5] = { {0,1,2,3,4}, {5,6,0,7,8}, {9,10,11,12,13} };

    const int r0   = 2 * ty;             // tile row of px0
    const int off0 = (h0 + r0) * WW + (w0 + tx);
    const int off1 = off0 + WW;

    const float* bfb = bf + (size_t)b * 14 * PLANE;
    const float* bf0 = bfb + off0;
    const float* bf1 = bfb + off1;

    u64t a0l = 0, a0h = 0, c0l = 0, c0h = 0;   // px0 ang/cond (class pairs)
    u64t a1l = 0, a1h = 0, c1l = 0, c1h = 0;   // px1

    #pragma unroll
    for (int s = 0; s < 4; ++s) {              // smem row = r0 + s
        const int sh = r0 + s;
        #pragma unroll
        for (int j = 0; j < 5; ++j) {
            const ulonglong2 u2 =
                *reinterpret_cast<const ulonglong2*>(&s_u[sh][tx + j]);
            const float m = s_m[sh][tx + j];
            if (s <= 2 && !(s == 1 && j == 2)) {       // px0 tap, dz = s
                const u64t g = g2[(int)gidx[s][j]];
                a0l = ffma2(g, u2.x, a0l);
                a0h = ffma2(g, u2.y, a0h);
                const float bm = bf0[(int)ktab[s][j] * PLANE] * m;
                const u64t bm2 = pack2(bm, bm);
                c0l = ffma2(bm2, u2.x, c0l);
                c0h = ffma2(bm2, u2.y, c0h);
            }
            if (s >= 1 && !(s == 2 && j == 2)) {       // px1 tap, dz = s-1
                const u64t g = g2[(int)gidx[s - 1][j]];
                a1l = ffma2(g, u2.x, a1l);
                a1h = ffma2(g, u2.y, a1h);
                const float bm = bf1[(int)ktab[s - 1][j] * PLANE] * m;
                const u64t bm2 = pack2(bm, bm);
                c1l = ffma2(bm2, u2.x, c1l);
                c1h = ffma2(bm2, u2.y, c1h);
            }
        }
    }

    // ---- Epilogue: both pixels
    const float  mc0 = s_m[r0 + 1][tx + 2];
    const float  mc1 = s_m[r0 + 2][tx + 2];
    const float4 uc0 = s_u[r0 + 1][tx + 2];
    const float4 uc1 = s_u[r0 + 2][tx + 2];

    write_px<OUT_PLANAR>(xout, b, off0, a0l, a0h, c0l, c0h, mc0, uc0);
    write_px<OUT_PLANAR>(xout, b, off1, a1l, a1h, c1l, c1h, mc1, uc1);
}

extern "C" void kernel_launch(void* const* d_in, const int* in_sizes, int n_in,
                              void* d_out, int out_size)
{
    const float* x    = (const float*)d_in[0];  // [16,4,64,512]
    const float* bf   = (const float*)d_in[1];  // [16,1,14,64,512]
    const float* mask = (const float*)d_in[2];  // [16,1,64,512]
    float* out = (float*)d_out;

    float4* ua = nullptr;
    float4* ub = nullptr;
    cudaGetSymbolAddress((void**)&ua, g_uA);
    cudaGetSymbolAddress((void**)&ub, g_uB);

    dim3 block(TW, TYN, 1);                 // 256 threads, 2 px/thread (H)
    dim3 grid(WW / TW, HH / TH, BATCH);     // 8 x 8 x 16 = 1024 blocks

    crf_iter_kernel<true,  false><<<grid, block>>>(x,          bf, mask, (float*)ua);
    crf_iter_kernel<false, false><<<grid, block>>>((float*)ua, bf, mask, (float*)ub);
    crf_iter_kernel<false, true ><<<grid, block>>>((float*)ub, bf, mask, out);
}